// round 7
// baseline (speedup 1.0000x reference)
#include <cuda_runtime.h>
#include <cstdint>
#include <cstddef>

// STPCell fused kernel, R6: cp.async smem ring for X/U streaming (no register
// pipeline, no barriers -- each thread consumes only its own staged 16B),
// 4 CTAs/SM occupancy, deferred 4-batch shuffle reduction.

#define HH   1024
#define IND  512
#define BB   32
#define ND   4                         // pipeline depth (stages)
#define BSTRIDE ((size_t)HH * HH * 4)  // bytes between batches of X/U

__device__ __forceinline__ float sigf(float v) {
    return 1.0f / (1.0f + __expf(-v));
}

__device__ __forceinline__ void cp16(uint32_t saddr, const void* gaddr) {
    asm volatile("cp.async.cg.shared.global [%0], [%1], 16;\n"
                 :: "r"(saddr), "l"(gaddr));
}
#define CP_COMMIT() asm volatile("cp.async.commit_group;\n" ::: "memory")
#define CP_WAIT(n)  asm volatile("cp.async.wait_group %0;\n" :: "n"(n) : "memory")

__global__ __launch_bounds__(256, 4) void stp_main(
    const float* __restrict__ x_in,   // (IN, B)
    const float* __restrict__ h,      // (B, H)
    const float* __restrict__ X,      // (B, H, H)
    const float* __restrict__ U,      // (B, H, H)
    const float* __restrict__ c_x,    // (H, H)
    const float* __restrict__ c_u,    // (H, H)
    const float* __restrict__ c_U,    // (H, H)
    const float* __restrict__ c_h,    // (H, 1)
    const float* __restrict__ w,      // (H, H)
    const float* __restrict__ p,      // (H, IN)
    const float* __restrict__ bias,   // (H, 1)
    float* __restrict__ out)          // (B, H)
{
    const int j    = blockIdx.x;
    const int tid  = threadIdx.x;
    const int lane = tid & 31;
    const int warp = tid >> 5;
    const int rowP = j * (HH / 4) + tid;     // float4 idx of (j, 4t..4t+3)

    __shared__ float4 xst[ND][256];
    __shared__ float4 ust[ND][256];
    __shared__ float  sred[8][BB];
    __shared__ float  px_s[BB];
    __shared__ float  hj_s[BB];

    const float4* __restrict__ h4 = reinterpret_cast<const float4*>(h);

    // ---- prologue constant loads ----
    const float4 cxv = reinterpret_cast<const float4*>(c_x)[rowP];
    const float4 cuv = reinterpret_cast<const float4*>(c_u)[rowP];
    const float4 cUv = reinterpret_cast<const float4*>(c_U)[rowP];
    const float4 wv  = reinterpret_cast<const float4*>(w)[rowP];

    // ---- cp.async ring: fill stages for batches 0..ND-2 ----
    const char* Xg = reinterpret_cast<const char*>(X) + (size_t)rowP * 16;
    const char* Ug = reinterpret_cast<const char*>(U) + (size_t)rowP * 16;
    const uint32_t xs0 = (uint32_t)__cvta_generic_to_shared(&xst[0][tid]);
    const uint32_t us0 = (uint32_t)__cvta_generic_to_shared(&ust[0][tid]);

    #pragma unroll
    for (int s = 0; s < ND - 1; ++s) {
        cp16(xs0 + s * 4096, Xg + (size_t)s * BSTRIDE);
        cp16(us0 + s * 4096, Ug + (size_t)s * BSTRIDE);
        CP_COMMIT();
    }

    // h register pipeline (1-deep): batches 0 and 1
    float4 h0 = __ldg(h4 + tid);
    float4 h1 = __ldg(h4 + (HH / 4) + tid);

    if (tid < BB) hj_s[tid] = h[tid * HH + j];

    // ---- (p @ x)[j, 0..31]: 8 segments of 64 i, b = lane ----
    {
        const int b   = tid & 31;
        const int seg = tid >> 5;
        const float* prow = p + j * IND;
        float a = 0.0f;
        #pragma unroll 8
        for (int i = seg * 64; i < seg * 64 + 64; ++i)
            a = fmaf(prow[i], x_in[i * BB + b], a);
        sred[seg][b] = a;
    }
    __syncthreads();
    if (tid < BB) {
        float s = 0.0f;
        #pragma unroll
        for (int q = 0; q < 8; ++q) s += sred[q][tid];
        px_s[tid] = s;
    }
    __syncthreads();            // sred free for epilogue partials

    // ---- per-(j,k) sigmoid constants, once, in registers ----
    float4 zx, zu, uc;
    zx.x = 0.001f + 0.099f * sigf(cxv.x);
    zx.y = 0.001f + 0.099f * sigf(cxv.y);
    zx.z = 0.001f + 0.099f * sigf(cxv.z);
    zx.w = 0.001f + 0.099f * sigf(cxv.w);
    zu.x = 0.001f + 0.099f * sigf(cuv.x);
    zu.y = 0.001f + 0.099f * sigf(cuv.y);
    zu.z = 0.001f + 0.099f * sigf(cuv.z);
    zu.w = 0.001f + 0.099f * sigf(cuv.w);
    uc.x = 0.9f * sigf(cUv.x);
    uc.y = 0.9f * sigf(cUv.y);
    uc.z = 0.9f * sigf(cUv.z);
    uc.w = 0.9f * sigf(cUv.w);

    // ---- streaming loop: 8 groups x 4 batches, barrier-free async ring ----
    #pragma unroll 1
    for (int g = 0; g < 8; ++g) {
        float a[4] = {0.0f, 0.0f, 0.0f, 0.0f};

        #pragma unroll
        for (int q = 0; q < 4; ++q) {
            const int b = g * 4 + q;

            // batch b's stage is complete once <= ND-2 groups are pending
            CP_WAIT(ND - 2);
            const float4 x0 = xst[b & (ND - 1)][tid];
            const float4 u0 = ust[b & (ND - 1)][tid];

            // prefetch batch b+ND-1 into its ring slot (clamped re-fetch at end)
            {
                const int bp = (b + ND - 1 < BB) ? (b + ND - 1) : (BB - 1);
                const int sl = (b + ND - 1) & (ND - 1);
                cp16(xs0 + sl * 4096, Xg + (size_t)bp * BSTRIDE);
                cp16(us0 + sl * 4096, Ug + (size_t)bp * BSTRIDE);
                CP_COMMIT();
            }
            // prefetch h for batch b+2
            const int bh = (b + 2 < BB) ? (b + 2) : (BB - 1);
            const float4 hn = __ldg(h4 + bh * (HH / 4) + tid);

            const float hj = hj_s[b];

            // X_new = fma(z_x, 1-X, X) - U*(X*hj)
            // U_new = Ucap*(z_u+hj) + U*((1-z_u) - Ucap*hj), clip [Ucap,1]
            // a[q] += (w * U_new * X_new) * h[b,k]
            #define STP_PROC(C)                                             \
            {                                                               \
                float xx = x0.C, uu = u0.C;                                 \
                float xnew = fmaf(zx.C, 1.0f - xx, xx);                     \
                xnew = fmaf(-uu, xx * hj, xnew);                            \
                float addu = uc.C * (zu.C + hj);                            \
                float cofu = fmaf(-uc.C, hj, 1.0f - zu.C);                  \
                float unew = fmaf(uu, cofu, addu);                          \
                unew = fminf(fmaxf(unew, uc.C), 1.0f);                     \
                a[q] = fmaf(wv.C * unew * xnew, h0.C, a[q]);                \
            }
            STP_PROC(x) STP_PROC(y) STP_PROC(z) STP_PROC(w)
            #undef STP_PROC

            h0 = h1; h1 = hn;
        }

        // 4 interleaved shuffle trees (independent chains overlap)
        #pragma unroll
        for (int o = 16; o > 0; o >>= 1) {
            a[0] += __shfl_xor_sync(0xffffffffu, a[0], o);
            a[1] += __shfl_xor_sync(0xffffffffu, a[1], o);
            a[2] += __shfl_xor_sync(0xffffffffu, a[2], o);
            a[3] += __shfl_xor_sync(0xffffffffu, a[3], o);
        }
        if (lane == 0) {
            sred[warp][g * 4 + 0] = a[0];
            sred[warp][g * 4 + 1] = a[1];
            sred[warp][g * 4 + 2] = a[2];
            sred[warp][g * 4 + 3] = a[3];
        }
    }
    __syncthreads();

    // ---- finalize: thread b (< 32) writes out[b, j] ----
    if (tid < BB) {
        const int b = tid;
        float rec = 0.0f;
        #pragma unroll
        for (int q = 0; q < 8; ++q) rec += sred[q][b];

        float pre = rec + px_s[b] + bias[j];
        float zh  = 0.5f * sigf(c_h[j]);          // E_H = 0.5
        float hbj = hj_s[b];                      // == h[b*HH + j]
        out[b * HH + j] = fmaf(zh, sigf(pre) - hbj, hbj);
    }
}

// ---------------------------------------------------------------------------
// Inputs (metadata order): x, h, X, U, c_x, c_u, c_U, c_h, w, p, b
// ---------------------------------------------------------------------------
extern "C" void kernel_launch(void* const* d_in, const int* in_sizes, int n_in,
                              void* d_out, int out_size)
{
    const float* x_in = (const float*)d_in[0];
    const float* h    = (const float*)d_in[1];
    const float* X    = (const float*)d_in[2];
    const float* U    = (const float*)d_in[3];
    const float* c_x  = (const float*)d_in[4];
    const float* c_u  = (const float*)d_in[5];
    const float* c_U  = (const float*)d_in[6];
    const float* c_h  = (const float*)d_in[7];
    const float* w    = (const float*)d_in[8];
    const float* p    = (const float*)d_in[9];
    const float* bias = (const float*)d_in[10];
    float* out = (float*)d_out;

    stp_main<<<HH, 256>>>(x_in, h, X, U, c_x, c_u, c_U, c_h, w, p, bias, out);
}